// round 8
// baseline (speedup 1.0000x reference)
#include <cuda_runtime.h>
#include <stdint.h>

#define F_IN 128
#define HID  16
#define NCLS 8
#define MAX_N 100000
#define MAX_E 3200000
#define T 256
#define NB_SCAN ((MAX_N + T - 1) / T)   // 391

__device__ int   g_ideg  [MAX_N];       // degree WITHOUT self loop
__device__ int   g_rowptr[MAX_N];
__device__ int   g_cursor[MAX_N];
__device__ int   g_bsum  [NB_SCAN];
__device__ int   g_csr   [MAX_E];       // src ids grouped by dst
__device__ float g_dinv  [MAX_N];
__device__ float g_h1s   [MAX_N * HID];   // dinv * (x@W1)
__device__ float g_h2s   [MAX_N * NCLS];  // dinv * h2

// 0) zero int degrees (scratch persists across graph replays -> must reset)
__global__ void k_zero(int n) {
    int i = blockIdx.x * blockDim.x + threadIdx.x;
    if (i < n) g_ideg[i] = 0;
}

// 1) int degree histogram over dst, int4-vectorized
__global__ void k_hist(const int* __restrict__ dst, int e) {
    int i = blockIdx.x * blockDim.x + threadIdx.x;
    int e4 = e >> 2;
    if (i < e4) {
        int4 d = ((const int4*)dst)[i];
        atomicAdd(&g_ideg[d.x], 1);
        atomicAdd(&g_ideg[d.y], 1);
        atomicAdd(&g_ideg[d.z], 1);
        atomicAdd(&g_ideg[d.w], 1);
    } else {
        int base = e4 * 4 + (i - e4);
        if (base < e) atomicAdd(&g_ideg[dst[base]], 1);
    }
}

// 2) per-block exclusive scan of ideg -> rowptr (local), block sums -> bsum
__global__ void k_scan_part(int n) {
    __shared__ int s[T];
    int i = blockIdx.x * T + threadIdx.x;
    int v = (i < n) ? g_ideg[i] : 0;
    s[threadIdx.x] = v;
    __syncthreads();
    #pragma unroll
    for (int off = 1; off < T; off <<= 1) {
        int t = (threadIdx.x >= off) ? s[threadIdx.x - off] : 0;
        __syncthreads();
        s[threadIdx.x] += t;
        __syncthreads();
    }
    int incl = s[threadIdx.x];
    if (i < n) g_rowptr[i] = incl - v;            // exclusive
    if (threadIdx.x == T - 1) g_bsum[blockIdx.x] = incl;
}

// 3) xw1 fused: h1 = x@W1; dinv = rsqrt(ideg+1); h1s = dinv*h1
//    (profiled launch index 3)
__global__ void k_xw1_fused(const float* __restrict__ x,
                            const float* __restrict__ W1, int n) {
    __shared__ float sW1[F_IN * HID];
    for (int i = threadIdx.x; i < F_IN * HID; i += blockDim.x)
        sW1[i] = W1[i];
    __syncthreads();

    int gid = blockIdx.x * blockDim.x + threadIdx.x;
    int node = gid / HID;
    int j    = gid % HID;
    if (node >= n) return;

    const float* xr = x + (size_t)node * F_IN;
    float acc = 0.0f;
    #pragma unroll 16
    for (int k = 0; k < F_IN; k++)
        acc = fmaf(__ldg(xr + k), sW1[k * HID + j], acc);

    float di = rsqrtf((float)g_ideg[node] + 1.0f);
    if (j == 0) g_dinv[node] = di;
    g_h1s[node * HID + j] = di * acc;
}

// 4) scan of block sums (single block)
__global__ void k_scan_top(int nb) {
    __shared__ int s[512];
    int v = (threadIdx.x < nb) ? g_bsum[threadIdx.x] : 0;
    s[threadIdx.x] = v;
    __syncthreads();
    #pragma unroll
    for (int off = 1; off < 512; off <<= 1) {
        int t = (threadIdx.x >= off) ? s[threadIdx.x - off] : 0;
        __syncthreads();
        s[threadIdx.x] += t;
        __syncthreads();
    }
    if (threadIdx.x < nb) g_bsum[threadIdx.x] = s[threadIdx.x] - v;  // exclusive
}

// 5) add block offsets; init cursor = rowptr
__global__ void k_scan_add(int n) {
    int i = blockIdx.x * T + threadIdx.x;
    if (i < n) {
        int r = g_rowptr[i] + g_bsum[blockIdx.x];
        g_rowptr[i] = r;
        g_cursor[i] = r;
    }
}

// 6) CSR scatter: group src ids by dst (4 edges per thread)
__global__ void k_csr_scatter(const int* __restrict__ src,
                              const int* __restrict__ dst, int e) {
    int i = blockIdx.x * blockDim.x + threadIdx.x;
    int e4 = e >> 2;
    if (i < e4) {
        int4 s = ((const int4*)src)[i];
        int4 d = ((const int4*)dst)[i];
        g_csr[atomicAdd(&g_cursor[d.x], 1)] = s.x;
        g_csr[atomicAdd(&g_cursor[d.y], 1)] = s.y;
        g_csr[atomicAdd(&g_cursor[d.z], 1)] = s.z;
        g_csr[atomicAdd(&g_cursor[d.w], 1)] = s.w;
    } else {
        int base = e4 * 4 + (i - e4);
        if (base < e)
            g_csr[atomicAdd(&g_cursor[dst[base]], 1)] = src[base];
    }
}

// 7) layer-1 CSR aggregation + FUSED layer-2 transform.
//    Warp per node: lanes (es=lane/4, j=lane%4) gather neighbor h1s rows,
//    register-accumulate, shfl-reduce, then relu(dinv*agg+b1)@W2 -> h2s.
__global__ void k_csr_l1(const float* __restrict__ b1,
                         const float* __restrict__ W2, int n) {
    __shared__ float sW2[HID * NCLS];
    __shared__ float sb1[HID];
    __shared__ float sv[8][HID];
    int t = threadIdx.x;
    if (t < HID * NCLS) sW2[t] = W2[t];
    if (t < HID) sb1[t] = b1[t];
    __syncthreads();

    int warp = t >> 5, lane = t & 31;
    int node = blockIdx.x * 8 + warp;
    if (node >= n) return;

    int start = g_rowptr[node];
    int deg   = g_ideg[node];
    int es = lane >> 2, j = lane & 3;

    float4 acc = make_float4(0.f, 0.f, 0.f, 0.f);
    for (int k = es; k < deg; k += 8) {
        int s = g_csr[start + k];               // broadcast within 4-lane group
        float4 h = *(const float4*)(g_h1s + s * HID + j * 4);
        acc.x += h.x; acc.y += h.y; acc.z += h.z; acc.w += h.w;
    }
    #pragma unroll
    for (int off = 16; off >= 4; off >>= 1) {
        acc.x += __shfl_down_sync(0xffffffffu, acc.x, off);
        acc.y += __shfl_down_sync(0xffffffffu, acc.y, off);
        acc.z += __shfl_down_sync(0xffffffffu, acc.z, off);
        acc.w += __shfl_down_sync(0xffffffffu, acc.w, off);
    }

    float di = g_dinv[node];
    if (lane < 4) {
        float4 self = *(const float4*)(g_h1s + node * HID + j * 4);
        sv[warp][j * 4 + 0] = fmaxf(fmaf(di, acc.x + self.x, sb1[j * 4 + 0]), 0.f);
        sv[warp][j * 4 + 1] = fmaxf(fmaf(di, acc.y + self.y, sb1[j * 4 + 1]), 0.f);
        sv[warp][j * 4 + 2] = fmaxf(fmaf(di, acc.z + self.z, sb1[j * 4 + 2]), 0.f);
        sv[warp][j * 4 + 3] = fmaxf(fmaf(di, acc.w + self.w, sb1[j * 4 + 3]), 0.f);
    }
    __syncwarp();
    if (lane < NCLS) {
        float a = 0.f;
        #pragma unroll
        for (int jj = 0; jj < HID; jj++)
            a = fmaf(sv[warp][jj], sW2[jj * NCLS + lane], a);
        g_h2s[node * NCLS + lane] = di * a;
    }
}

// 8) layer-2 CSR aggregation + FUSED log_softmax.
//    Warp per node: lanes (es=lane/2, j=lane%2) gather h2s rows.
__global__ void k_csr_l2(const float* __restrict__ b2,
                         float* __restrict__ out, int n) {
    __shared__ float sb2[NCLS];
    int t = threadIdx.x;
    if (t < NCLS) sb2[t] = b2[t];
    __syncthreads();

    int warp = t >> 5, lane = t & 31;
    int node = blockIdx.x * 8 + warp;
    if (node >= n) return;

    int start = g_rowptr[node];
    int deg   = g_ideg[node];
    int es = lane >> 1, j = lane & 1;

    float4 acc = make_float4(0.f, 0.f, 0.f, 0.f);
    for (int k = es; k < deg; k += 16) {
        int s = g_csr[start + k];
        float4 h = *(const float4*)(g_h2s + s * NCLS + j * 4);
        acc.x += h.x; acc.y += h.y; acc.z += h.z; acc.w += h.w;
    }
    #pragma unroll
    for (int off = 16; off >= 2; off >>= 1) {
        acc.x += __shfl_down_sync(0xffffffffu, acc.x, off);
        acc.y += __shfl_down_sync(0xffffffffu, acc.y, off);
        acc.z += __shfl_down_sync(0xffffffffu, acc.z, off);
        acc.w += __shfl_down_sync(0xffffffffu, acc.w, off);
    }

    float di = g_dinv[node];
    float4 z = make_float4(0.f, 0.f, 0.f, 0.f);
    float m_local = -1e30f;
    if (lane < 2) {
        float4 self = *(const float4*)(g_h2s + node * NCLS + j * 4);
        z.x = fmaf(di, acc.x + self.x, sb2[j * 4 + 0]);
        z.y = fmaf(di, acc.y + self.y, sb2[j * 4 + 1]);
        z.z = fmaf(di, acc.z + self.z, sb2[j * 4 + 2]);
        z.w = fmaf(di, acc.w + self.w, sb2[j * 4 + 3]);
        m_local = fmaxf(fmaxf(z.x, z.y), fmaxf(z.z, z.w));
    }
    float m = fmaxf(m_local, __shfl_xor_sync(0xffffffffu, m_local, 1));
    float s_local = 0.f;
    if (lane < 2)
        s_local = expf(z.x - m) + expf(z.y - m) + expf(z.z - m) + expf(z.w - m);
    float s_tot = s_local + __shfl_xor_sync(0xffffffffu, s_local, 1);
    if (lane < 2) {
        float lse = m + logf(s_tot);
        *(float4*)(out + node * NCLS + j * 4) =
            make_float4(z.x - lse, z.y - lse, z.z - lse, z.w - lse);
    }
}

// ---------------------------------------------------------------------------
extern "C" void kernel_launch(void* const* d_in, const int* in_sizes, int n_in,
                              void* d_out, int out_size) {
    const float* x  = (const float*)d_in[0];
    const int*   ei = (const int*)d_in[1];    // [2, E] int32
    const float* W1 = (const float*)d_in[2];
    const float* b1 = (const float*)d_in[3];
    const float* W2 = (const float*)d_in[4];
    const float* b2 = (const float*)d_in[5];
    float*       out = (float*)d_out;

    const int n = in_sizes[0] / F_IN;      // 100000
    const int e = in_sizes[1] / 2;         // 3200000
    const int* src = ei;
    const int* dst = ei + e;

    int nb   = (n + T - 1) / T;            // scan blocks (391)
    int e4t  = (e >> 2) + (e & 3);

    k_zero<<<nb, T>>>(n);                                               // 0
    k_hist<<<(e4t + T - 1) / T, T>>>(dst, e);                           // 1
    k_scan_part<<<nb, T>>>(n);                                          // 2
    k_xw1_fused<<<((long long)n * HID + T - 1) / T, T>>>(x, W1, n);     // 3 (profiled)
    k_scan_top<<<1, 512>>>(nb);                                         // 4
    k_scan_add<<<nb, T>>>(n);                                           // 5
    k_csr_scatter<<<(e4t + T - 1) / T, T>>>(src, dst, e);               // 6
    k_csr_l1<<<(n + 7) / 8, T>>>(b1, W2, n);                            // 7
    k_csr_l2<<<(n + 7) / 8, T>>>(b2, out, n);                           // 8
}

// round 9
// speedup vs baseline: 1.3362x; 1.3362x over previous
#include <cuda_runtime.h>
#include <stdint.h>

#define F_IN 128
#define HID  16
#define NCLS 8
#define MAX_N 100000

__device__ float g_deg [MAX_N];
__device__ float g_dinv[MAX_N];
__device__ float g_h1s [MAX_N * HID];   // dinv * (x@W1)
__device__ float g_agg1[MAX_N * HID];   // pre-scale accumulator: final = dinv*agg1
__device__ float g_h2s [MAX_N * NCLS];  // dinv * h2
__device__ float g_agg2[MAX_N * NCLS];

__device__ __forceinline__ void red_add_v4(float* p, float4 v) {
    asm volatile("red.global.add.v4.f32 [%0], {%1, %2, %3, %4};"
                 :: "l"(p), "f"(v.x), "f"(v.y), "f"(v.z), "f"(v.w) : "memory");
}

// 0) deg init: self-loop contributes 1
__global__ void k_init_deg(int n) {
    int i = blockIdx.x * blockDim.x + threadIdx.x;
    if (i < n) g_deg[i] = 1.0f;
}

// 1) degree scatter, int4-vectorized (4 edges per thread)
__global__ void k_deg_scatter(const int* __restrict__ dst, int e) {
    int i = blockIdx.x * blockDim.x + threadIdx.x;
    int e4 = e >> 2;
    if (i < e4) {
        int4 d = ((const int4*)dst)[i];
        atomicAdd(&g_deg[d.x], 1.0f);
        atomicAdd(&g_deg[d.y], 1.0f);
        atomicAdd(&g_deg[d.z], 1.0f);
        atomicAdd(&g_deg[d.w], 1.0f);
    } else {
        int base = e4 * 4 + (i - e4);
        if (base < e) atomicAdd(&g_deg[dst[base]], 1.0f);
    }
}

// 2) dinv = rsqrt(deg)
__global__ void k_dinv(int n) {
    int i = blockIdx.x * blockDim.x + threadIdx.x;
    if (i < n) g_dinv[i] = rsqrtf(g_deg[i]);
}

// 3) xw1 register-tiled: 4 threads/node, float4 x loads, W1 as float4 in shared.
//    h1s = dinv * (x@W1); agg1 = h1s (self-loop, pre-scale form). [profiled]
__global__ void k_xw1(const float* __restrict__ x,
                      const float* __restrict__ W1, int n) {
    __shared__ float4 sW1[F_IN * 4];  // sW1[k*4+jg] = W1[k][4jg .. 4jg+3]
    int t = threadIdx.x;
    for (int i = t; i < F_IN * 4; i += blockDim.x)
        sW1[i] = ((const float4*)W1)[i];
    __syncthreads();

    int gid = blockIdx.x * blockDim.x + t;
    int node = gid >> 2;
    int jg   = gid & 3;
    if (node >= n) return;

    const float4* xr = (const float4*)(x + (size_t)node * F_IN);
    float4 acc = make_float4(0.f, 0.f, 0.f, 0.f);
    #pragma unroll
    for (int k4 = 0; k4 < F_IN / 4; k4++) {
        float4 xv = __ldg(xr + k4);
        float4 w0 = sW1[(k4 * 4 + 0) * 4 + jg];
        acc.x = fmaf(xv.x, w0.x, acc.x); acc.y = fmaf(xv.x, w0.y, acc.y);
        acc.z = fmaf(xv.x, w0.z, acc.z); acc.w = fmaf(xv.x, w0.w, acc.w);
        float4 w1 = sW1[(k4 * 4 + 1) * 4 + jg];
        acc.x = fmaf(xv.y, w1.x, acc.x); acc.y = fmaf(xv.y, w1.y, acc.y);
        acc.z = fmaf(xv.y, w1.z, acc.z); acc.w = fmaf(xv.y, w1.w, acc.w);
        float4 w2 = sW1[(k4 * 4 + 2) * 4 + jg];
        acc.x = fmaf(xv.z, w2.x, acc.x); acc.y = fmaf(xv.z, w2.y, acc.y);
        acc.z = fmaf(xv.z, w2.z, acc.z); acc.w = fmaf(xv.z, w2.w, acc.w);
        float4 w3 = sW1[(k4 * 4 + 3) * 4 + jg];
        acc.x = fmaf(xv.w, w3.x, acc.x); acc.y = fmaf(xv.w, w3.y, acc.y);
        acc.z = fmaf(xv.w, w3.z, acc.z); acc.w = fmaf(xv.w, w3.w, acc.w);
    }

    float di = g_dinv[node];   // broadcast within 4-lane group
    float4 hs = make_float4(di * acc.x, di * acc.y, di * acc.z, di * acc.w);
    *(float4*)(g_h1s  + node * HID + jg * 4) = hs;
    *(float4*)(g_agg1 + node * HID + jg * 4) = hs;
}

// 4) layer-1 edge scatter: 4 threads/edge, 2 edges/thread, v4 RED
__global__ void k_edge1(const int* __restrict__ src,
                        const int* __restrict__ dst, int e) {
    int h = (e + 1) >> 1;
    long long gid = (long long)blockIdx.x * blockDim.x + threadIdx.x;
    int q = (int)(gid >> 2);
    int j = (int)(gid & 3);
    if (q >= h) return;
    int eA = q, eB = q + h;
    bool hasB = eB < e;

    int sA = src[eA], dA = dst[eA];
    int sB = 0, dB = 0;
    if (hasB) { sB = src[eB]; dB = dst[eB]; }

    float4 hA = *(const float4*)(g_h1s + sA * HID + j * 4);
    red_add_v4(g_agg1 + dA * HID + j * 4, hA);
    if (hasB) {
        float4 hB = *(const float4*)(g_h1s + sB * HID + j * 4);
        red_add_v4(g_agg1 + dB * HID + j * 4, hB);
    }
}

// 5) h2 = relu(dinv*agg1 + b1) @ W2; h2s = dinv*h2; agg2 = h2s (self loop)
__global__ void k_layer2(const float* __restrict__ b1,
                         const float* __restrict__ W2, int n) {
    __shared__ float sW2[HID * NCLS];
    __shared__ float sb1[HID];
    if (threadIdx.x < HID * NCLS) sW2[threadIdx.x] = W2[threadIdx.x];
    if (threadIdx.x < HID) sb1[threadIdx.x] = b1[threadIdx.x];
    __syncthreads();

    int gid = blockIdx.x * blockDim.x + threadIdx.x;
    int node = gid / NCLS;
    int c    = gid % NCLS;
    if (node >= n) return;

    float di = g_dinv[node];
    float acc = 0.0f;
    #pragma unroll
    for (int j = 0; j < HID; j++) {
        float v = fmaf(di, g_agg1[node * HID + j], sb1[j]);
        v = fmaxf(v, 0.0f);
        acc = fmaf(v, sW2[j * NCLS + c], acc);
    }
    float hs = di * acc;
    g_h2s [node * NCLS + c] = hs;
    g_agg2[node * NCLS + c] = hs;
}

// 6) layer-2 edge scatter: 2 threads/edge, 2 edges/thread, v4 RED
__global__ void k_edge2(const int* __restrict__ src,
                        const int* __restrict__ dst, int e) {
    int h = (e + 1) >> 1;
    long long gid = (long long)blockIdx.x * blockDim.x + threadIdx.x;
    int q = (int)(gid >> 1);
    int j = (int)(gid & 1);
    if (q >= h) return;
    int eA = q, eB = q + h;
    bool hasB = eB < e;

    int sA = src[eA], dA = dst[eA];
    int sB = 0, dB = 0;
    if (hasB) { sB = src[eB]; dB = dst[eB]; }

    float4 hA = *(const float4*)(g_h2s + sA * NCLS + j * 4);
    red_add_v4(g_agg2 + dA * NCLS + j * 4, hA);
    if (hasB) {
        float4 hB = *(const float4*)(g_h2s + sB * NCLS + j * 4);
        red_add_v4(g_agg2 + dB * NCLS + j * 4, hB);
    }
}

// 7) logits = dinv*agg2 + b2 -> log_softmax
__global__ void k_logsoftmax(const float* __restrict__ b2,
                             float* __restrict__ out, int n) {
    __shared__ float sb2[NCLS];
    if (threadIdx.x < NCLS) sb2[threadIdx.x] = b2[threadIdx.x];
    __syncthreads();

    int i = blockIdx.x * blockDim.x + threadIdx.x;
    if (i >= n) return;

    float di = g_dinv[i];
    float4 a = *(const float4*)(g_agg2 + i * NCLS);
    float4 b = *(const float4*)(g_agg2 + i * NCLS + 4);
    float z[NCLS] = {fmaf(di, a.x, sb2[0]), fmaf(di, a.y, sb2[1]),
                     fmaf(di, a.z, sb2[2]), fmaf(di, a.w, sb2[3]),
                     fmaf(di, b.x, sb2[4]), fmaf(di, b.y, sb2[5]),
                     fmaf(di, b.z, sb2[6]), fmaf(di, b.w, sb2[7])};
    float m = z[0];
    #pragma unroll
    for (int c = 1; c < NCLS; c++) m = fmaxf(m, z[c]);
    float sum = 0.0f;
    #pragma unroll
    for (int c = 0; c < NCLS; c++) sum += expf(z[c] - m);
    float lse = m + logf(sum);
    *(float4*)(out + i * NCLS)     = make_float4(z[0]-lse, z[1]-lse, z[2]-lse, z[3]-lse);
    *(float4*)(out + i * NCLS + 4) = make_float4(z[4]-lse, z[5]-lse, z[6]-lse, z[7]-lse);
}

// ---------------------------------------------------------------------------
extern "C" void kernel_launch(void* const* d_in, const int* in_sizes, int n_in,
                              void* d_out, int out_size) {
    const float* x  = (const float*)d_in[0];
    const int*   ei = (const int*)d_in[1];    // [2, E] int32
    const float* W1 = (const float*)d_in[2];
    const float* b1 = (const float*)d_in[3];
    const float* W2 = (const float*)d_in[4];
    const float* b2 = (const float*)d_in[5];
    float*       out = (float*)d_out;

    const int n = in_sizes[0] / F_IN;      // 100000
    const int e = in_sizes[1] / 2;         // 3200000
    const int* src = ei;
    const int* dst = ei + e;

    const int T = 256;
    int e4t = (e >> 2) + (e & 3);

    k_init_deg<<<(n + T - 1) / T, T>>>(n);                              // 0
    k_deg_scatter<<<(e4t + T - 1) / T, T>>>(dst, e);                    // 1
    k_dinv<<<(n + T - 1) / T, T>>>(n);                                  // 2
    k_xw1<<<((long long)n * 4 + T - 1) / T, T>>>(x, W1, n);             // 3 (profiled)
    {
        long long total = (long long)((e + 1) >> 1) * 4;
        k_edge1<<<(unsigned)((total + T - 1) / T), T>>>(src, dst, e);   // 4
    }
    k_layer2<<<((long long)n * NCLS + T - 1) / T, T>>>(b1, W2, n);      // 5
    {
        long long total = (long long)((e + 1) >> 1) * 2;
        k_edge2<<<(unsigned)((total + T - 1) / T), T>>>(src, dst, e);   // 6
    }
    k_logsoftmax<<<(n + T - 1) / T, T>>>(b2, out, n);                   // 7
}

// round 10
// speedup vs baseline: 1.4079x; 1.0537x over previous
#include <cuda_runtime.h>
#include <stdint.h>

#define F_IN 128
#define HID  16
#define NCLS 8
#define MAX_N 100000

__device__ float g_deg [MAX_N];
__device__ float g_dinv[MAX_N];
__device__ float g_h1s [MAX_N * HID];   // dinv * (x@W1)
__device__ float g_agg1[MAX_N * HID];   // pre-scale accumulator: final = dinv*agg1
__device__ float g_h2s [MAX_N * NCLS];  // dinv * h2
__device__ float g_agg2[MAX_N * NCLS];

__device__ __forceinline__ void red_add_v4(float* p, float4 v) {
    asm volatile("red.global.add.v4.f32 [%0], {%1, %2, %3, %4};"
                 :: "l"(p), "f"(v.x), "f"(v.y), "f"(v.z), "f"(v.w) : "memory");
}

// 0) deg init: self-loop contributes 1
__global__ void k_init_deg(int n) {
    int i = blockIdx.x * blockDim.x + threadIdx.x;
    if (i < n) g_deg[i] = 1.0f;
}

// 1) degree scatter, int4-vectorized (4 edges per thread)
__global__ void k_deg_scatter(const int* __restrict__ dst, int e) {
    int i = blockIdx.x * blockDim.x + threadIdx.x;
    int e4 = e >> 2;
    if (i < e4) {
        int4 d = ((const int4*)dst)[i];
        atomicAdd(&g_deg[d.x], 1.0f);
        atomicAdd(&g_deg[d.y], 1.0f);
        atomicAdd(&g_deg[d.z], 1.0f);
        atomicAdd(&g_deg[d.w], 1.0f);
    } else {
        int base = e4 * 4 + (i - e4);
        if (base < e) atomicAdd(&g_deg[dst[base]], 1.0f);
    }
}

// 2) dinv = rsqrt(deg)
__global__ void k_dinv(int n) {
    int i = blockIdx.x * blockDim.x + threadIdx.x;
    if (i < n) g_dinv[i] = rsqrtf(g_deg[i]);
}

// 3) xw1, W-amortized: thread = (slot, jg) handles 8 nodes x 4 outputs.
//    Per k4: 8 x-loads (LDG.128) + 4 W-loads (LDS.128) -> 128 FMAs.
//    h1s = dinv*(x@W1); agg1 = h1s (self-loop, pre-scale form). [profiled idx 3]
#define XW_ND 8
__global__ void __launch_bounds__(256) k_xw1(const float* __restrict__ x,
                                             const float* __restrict__ W1, int n) {
    __shared__ float4 sW1[F_IN * 4];  // sW1[k*4+jg] = W1[k][4jg..4jg+3]
    int t = threadIdx.x;
    for (int i = t; i < F_IN * 4; i += blockDim.x)
        sW1[i] = ((const float4*)W1)[i];
    __syncthreads();

    int slot = t >> 2;            // 0..63
    int jg   = t & 3;             // 0..3
    int base = blockIdx.x * (64 * XW_ND);

    int   node[XW_ND];
    bool  ok  [XW_ND];
    #pragma unroll
    for (int i = 0; i < XW_ND; i++) {
        node[i] = base + i * 64 + slot;
        ok[i]   = node[i] < n;
    }

    float4 acc[XW_ND];
    #pragma unroll
    for (int i = 0; i < XW_ND; i++) acc[i] = make_float4(0.f, 0.f, 0.f, 0.f);

    #pragma unroll 4
    for (int k4 = 0; k4 < F_IN / 4; k4++) {
        float4 w0 = sW1[(k4 * 4 + 0) * 4 + jg];
        float4 w1 = sW1[(k4 * 4 + 1) * 4 + jg];
        float4 w2 = sW1[(k4 * 4 + 2) * 4 + jg];
        float4 w3 = sW1[(k4 * 4 + 3) * 4 + jg];
        float4 xv[XW_ND];
        #pragma unroll
        for (int i = 0; i < XW_ND; i++)
            xv[i] = ok[i] ? __ldg((const float4*)(x + (size_t)node[i] * F_IN) + k4)
                          : make_float4(0.f, 0.f, 0.f, 0.f);
        #pragma unroll
        for (int i = 0; i < XW_ND; i++) {
            acc[i].x = fmaf(xv[i].x, w0.x, acc[i].x);
            acc[i].y = fmaf(xv[i].x, w0.y, acc[i].y);
            acc[i].z = fmaf(xv[i].x, w0.z, acc[i].z);
            acc[i].w = fmaf(xv[i].x, w0.w, acc[i].w);
            acc[i].x = fmaf(xv[i].y, w1.x, acc[i].x);
            acc[i].y = fmaf(xv[i].y, w1.y, acc[i].y);
            acc[i].z = fmaf(xv[i].y, w1.z, acc[i].z);
            acc[i].w = fmaf(xv[i].y, w1.w, acc[i].w);
            acc[i].x = fmaf(xv[i].z, w2.x, acc[i].x);
            acc[i].y = fmaf(xv[i].z, w2.y, acc[i].y);
            acc[i].z = fmaf(xv[i].z, w2.z, acc[i].z);
            acc[i].w = fmaf(xv[i].z, w2.w, acc[i].w);
            acc[i].x = fmaf(xv[i].w, w3.x, acc[i].x);
            acc[i].y = fmaf(xv[i].w, w3.y, acc[i].y);
            acc[i].z = fmaf(xv[i].w, w3.z, acc[i].z);
            acc[i].w = fmaf(xv[i].w, w3.w, acc[i].w);
        }
    }

    #pragma unroll
    for (int i = 0; i < XW_ND; i++) {
        if (!ok[i]) continue;
        float di = g_dinv[node[i]];
        float4 hs = make_float4(di * acc[i].x, di * acc[i].y,
                                di * acc[i].z, di * acc[i].w);
        *(float4*)(g_h1s  + node[i] * HID + jg * 4) = hs;
        *(float4*)(g_agg1 + node[i] * HID + jg * 4) = hs;
    }
}

// 4) layer-1 edge scatter: 4 threads/edge, 2 edges/thread, v4 RED
__global__ void k_edge1(const int* __restrict__ src,
                        const int* __restrict__ dst, int e) {
    int h = (e + 1) >> 1;
    long long gid = (long long)blockIdx.x * blockDim.x + threadIdx.x;
    int q = (int)(gid >> 2);
    int j = (int)(gid & 3);
    if (q >= h) return;
    int eA = q, eB = q + h;
    bool hasB = eB < e;

    int sA = src[eA], dA = dst[eA];
    int sB = 0, dB = 0;
    if (hasB) { sB = src[eB]; dB = dst[eB]; }

    float4 hA = *(const float4*)(g_h1s + sA * HID + j * 4);
    red_add_v4(g_agg1 + dA * HID + j * 4, hA);
    if (hasB) {
        float4 hB = *(const float4*)(g_h1s + sB * HID + j * 4);
        red_add_v4(g_agg1 + dB * HID + j * 4, hB);
    }
}

// 5) h2 = relu(dinv*agg1 + b1) @ W2; h2s = dinv*h2; agg2 = h2s (self loop)
__global__ void k_layer2(const float* __restrict__ b1,
                         const float* __restrict__ W2, int n) {
    __shared__ float sW2[HID * NCLS];
    __shared__ float sb1[HID];
    if (threadIdx.x < HID * NCLS) sW2[threadIdx.x] = W2[threadIdx.x];
    if (threadIdx.x < HID) sb1[threadIdx.x] = b1[threadIdx.x];
    __syncthreads();

    int gid = blockIdx.x * blockDim.x + threadIdx.x;
    int node = gid / NCLS;
    int c    = gid % NCLS;
    if (node >= n) return;

    float di = g_dinv[node];
    float acc = 0.0f;
    #pragma unroll
    for (int j = 0; j < HID; j++) {
        float v = fmaf(di, g_agg1[node * HID + j], sb1[j]);
        v = fmaxf(v, 0.0f);
        acc = fmaf(v, sW2[j * NCLS + c], acc);
    }
    float hs = di * acc;
    g_h2s [node * NCLS + c] = hs;
    g_agg2[node * NCLS + c] = hs;
}

// 6) layer-2 edge scatter: 2 threads/edge, 2 edges/thread, v4 RED
__global__ void k_edge2(const int* __restrict__ src,
                        const int* __restrict__ dst, int e) {
    int h = (e + 1) >> 1;
    long long gid = (long long)blockIdx.x * blockDim.x + threadIdx.x;
    int q = (int)(gid >> 1);
    int j = (int)(gid & 1);
    if (q >= h) return;
    int eA = q, eB = q + h;
    bool hasB = eB < e;

    int sA = src[eA], dA = dst[eA];
    int sB = 0, dB = 0;
    if (hasB) { sB = src[eB]; dB = dst[eB]; }

    float4 hA = *(const float4*)(g_h2s + sA * NCLS + j * 4);
    red_add_v4(g_agg2 + dA * NCLS + j * 4, hA);
    if (hasB) {
        float4 hB = *(const float4*)(g_h2s + sB * NCLS + j * 4);
        red_add_v4(g_agg2 + dB * NCLS + j * 4, hB);
    }
}

// 7) logits = dinv*agg2 + b2 -> log_softmax
__global__ void k_logsoftmax(const float* __restrict__ b2,
                             float* __restrict__ out, int n) {
    __shared__ float sb2[NCLS];
    if (threadIdx.x < NCLS) sb2[threadIdx.x] = b2[threadIdx.x];
    __syncthreads();

    int i = blockIdx.x * blockDim.x + threadIdx.x;
    if (i >= n) return;

    float di = g_dinv[i];
    float4 a = *(const float4*)(g_agg2 + i * NCLS);
    float4 b = *(const float4*)(g_agg2 + i * NCLS + 4);
    float z[NCLS] = {fmaf(di, a.x, sb2[0]), fmaf(di, a.y, sb2[1]),
                     fmaf(di, a.z, sb2[2]), fmaf(di, a.w, sb2[3]),
                     fmaf(di, b.x, sb2[4]), fmaf(di, b.y, sb2[5]),
                     fmaf(di, b.z, sb2[6]), fmaf(di, b.w, sb2[7])};
    float m = z[0];
    #pragma unroll
    for (int c = 1; c < NCLS; c++) m = fmaxf(m, z[c]);
    float sum = 0.0f;
    #pragma unroll
    for (int c = 0; c < NCLS; c++) sum += expf(z[c] - m);
    float lse = m + logf(sum);
    *(float4*)(out + i * NCLS)     = make_float4(z[0]-lse, z[1]-lse, z[2]-lse, z[3]-lse);
    *(float4*)(out + i * NCLS + 4) = make_float4(z[4]-lse, z[5]-lse, z[6]-lse, z[7]-lse);
}

// ---------------------------------------------------------------------------
extern "C" void kernel_launch(void* const* d_in, const int* in_sizes, int n_in,
                              void* d_out, int out_size) {
    const float* x  = (const float*)d_in[0];
    const int*   ei = (const int*)d_in[1];    // [2, E] int32
    const float* W1 = (const float*)d_in[2];
    const float* b1 = (const float*)d_in[3];
    const float* W2 = (const float*)d_in[4];
    const float* b2 = (const float*)d_in[5];
    float*       out = (float*)d_out;

    const int n = in_sizes[0] / F_IN;      // 100000
    const int e = in_sizes[1] / 2;         // 3200000
    const int* src = ei;
    const int* dst = ei + e;

    const int T = 256;
    int e4t = (e >> 2) + (e & 3);

    k_init_deg<<<(n + T - 1) / T, T>>>(n);                              // 0
    k_deg_scatter<<<(e4t + T - 1) / T, T>>>(dst, e);                    // 1
    k_dinv<<<(n + T - 1) / T, T>>>(n);                                  // 2
    k_xw1<<<(n + 64 * XW_ND - 1) / (64 * XW_ND), T>>>(x, W1, n);        // 3 (profiled)
    {
        long long total = (long long)((e + 1) >> 1) * 4;
        k_edge1<<<(unsigned)((total + T - 1) / T), T>>>(src, dst, e);   // 4
    }
    k_layer2<<<((long long)n * NCLS + T - 1) / T, T>>>(b1, W2, n);      // 5
    {
        long long total = (long long)((e + 1) >> 1) * 2;
        k_edge2<<<(unsigned)((total + T - 1) / T), T>>>(src, dst, e);   // 6
    }
    k_logsoftmax<<<(n + T - 1) / T, T>>>(b2, out, n);                   // 7
}

// round 11
// speedup vs baseline: 1.4740x; 1.0469x over previous
#include <cuda_runtime.h>
#include <stdint.h>

#define F_IN 128
#define HID  16
#define NCLS 8
#define MAX_N 100000

__device__ float g_deg [MAX_N];
__device__ float g_dinv[MAX_N];
__device__ float g_h1s [MAX_N * HID];   // dinv * (x@W1)
__device__ float g_agg1[MAX_N * HID];   // pre-scale accumulator: final = dinv*agg1
__device__ float g_h2s [MAX_N * NCLS];  // dinv * h2
__device__ float g_agg2[MAX_N * NCLS];

__device__ __forceinline__ void red_add_v4(float* p, float4 v) {
    asm volatile("red.global.add.v4.f32 [%0], {%1, %2, %3, %4};"
                 :: "l"(p), "f"(v.x), "f"(v.y), "f"(v.z), "f"(v.w) : "memory");
}

// 0) deg init: self-loop contributes 1
__global__ void k_init_deg(int n) {
    int i = blockIdx.x * blockDim.x + threadIdx.x;
    if (i < n) g_deg[i] = 1.0f;
}

// 1) degree scatter, int4-vectorized (4 edges per thread)
__global__ void k_deg_scatter(const int* __restrict__ dst, int e) {
    int i = blockIdx.x * blockDim.x + threadIdx.x;
    int e4 = e >> 2;
    if (i < e4) {
        int4 d = ((const int4*)dst)[i];
        atomicAdd(&g_deg[d.x], 1.0f);
        atomicAdd(&g_deg[d.y], 1.0f);
        atomicAdd(&g_deg[d.z], 1.0f);
        atomicAdd(&g_deg[d.w], 1.0f);
    } else {
        int base = e4 * 4 + (i - e4);
        if (base < e) atomicAdd(&g_deg[dst[base]], 1.0f);
    }
}

// 2) dinv = rsqrt(deg)
__global__ void k_dinv(int n) {
    int i = blockIdx.x * blockDim.x + threadIdx.x;
    if (i < n) g_dinv[i] = rsqrtf(g_deg[i]);
}

// 3) xw1, W-amortized, occupancy-tuned: thread = (slot, jg), 4 nodes x 4 outputs.
//    Per k4: 4 x-loads (LDG.128) + 4 W-loads (LDS.128) -> 64 FMAs.
//    h1s = dinv*(x@W1); agg1 = h1s (self-loop, pre-scale). [profiled idx 3]
#define XW_ND 4
__global__ void __launch_bounds__(256, 4) k_xw1(const float* __restrict__ x,
                                                const float* __restrict__ W1, int n) {
    __shared__ float4 sW1[F_IN * 4];  // sW1[k*4+jg] = W1[k][4jg..4jg+3]
    int t = threadIdx.x;
    for (int i = t; i < F_IN * 4; i += blockDim.x)
        sW1[i] = ((const float4*)W1)[i];
    __syncthreads();

    int slot = t >> 2;            // 0..63
    int jg   = t & 3;             // 0..3
    int base = blockIdx.x * (64 * XW_ND);

    int   node[XW_ND];
    bool  ok  [XW_ND];
    #pragma unroll
    for (int i = 0; i < XW_ND; i++) {
        node[i] = base + i * 64 + slot;
        ok[i]   = node[i] < n;
    }

    float4 acc[XW_ND];
    #pragma unroll
    for (int i = 0; i < XW_ND; i++) acc[i] = make_float4(0.f, 0.f, 0.f, 0.f);

    #pragma unroll 4
    for (int k4 = 0; k4 < F_IN / 4; k4++) {
        float4 w0 = sW1[(k4 * 4 + 0) * 4 + jg];
        float4 w1 = sW1[(k4 * 4 + 1) * 4 + jg];
        float4 w2 = sW1[(k4 * 4 + 2) * 4 + jg];
        float4 w3 = sW1[(k4 * 4 + 3) * 4 + jg];
        float4 xv[XW_ND];
        #pragma unroll
        for (int i = 0; i < XW_ND; i++)
            xv[i] = ok[i] ? __ldg((const float4*)(x + (size_t)node[i] * F_IN) + k4)
                          : make_float4(0.f, 0.f, 0.f, 0.f);
        #pragma unroll
        for (int i = 0; i < XW_ND; i++) {
            acc[i].x = fmaf(xv[i].x, w0.x, acc[i].x);
            acc[i].y = fmaf(xv[i].x, w0.y, acc[i].y);
            acc[i].z = fmaf(xv[i].x, w0.z, acc[i].z);
            acc[i].w = fmaf(xv[i].x, w0.w, acc[i].w);
            acc[i].x = fmaf(xv[i].y, w1.x, acc[i].x);
            acc[i].y = fmaf(xv[i].y, w1.y, acc[i].y);
            acc[i].z = fmaf(xv[i].y, w1.z, acc[i].z);
            acc[i].w = fmaf(xv[i].y, w1.w, acc[i].w);
            acc[i].x = fmaf(xv[i].z, w2.x, acc[i].x);
            acc[i].y = fmaf(xv[i].z, w2.y, acc[i].y);
            acc[i].z = fmaf(xv[i].z, w2.z, acc[i].z);
            acc[i].w = fmaf(xv[i].z, w2.w, acc[i].w);
            acc[i].x = fmaf(xv[i].w, w3.x, acc[i].x);
            acc[i].y = fmaf(xv[i].w, w3.y, acc[i].y);
            acc[i].z = fmaf(xv[i].w, w3.z, acc[i].z);
            acc[i].w = fmaf(xv[i].w, w3.w, acc[i].w);
        }
    }

    #pragma unroll
    for (int i = 0; i < XW_ND; i++) {
        if (!ok[i]) continue;
        float di = g_dinv[node[i]];
        float4 hs = make_float4(di * acc[i].x, di * acc[i].y,
                                di * acc[i].z, di * acc[i].w);
        *(float4*)(g_h1s  + node[i] * HID + jg * 4) = hs;
        *(float4*)(g_agg1 + node[i] * HID + jg * 4) = hs;
    }
}

// 4) layer-1 edge scatter: 4 threads/edge, 2 edges/thread, v4 RED
__global__ void k_edge1(const int* __restrict__ src,
                        const int* __restrict__ dst, int e) {
    int h = (e + 1) >> 1;
    long long gid = (long long)blockIdx.x * blockDim.x + threadIdx.x;
    int q = (int)(gid >> 2);
    int j = (int)(gid & 3);
    if (q >= h) return;
    int eA = q, eB = q + h;
    bool hasB = eB < e;

    int sA = src[eA], dA = dst[eA];
    int sB = 0, dB = 0;
    if (hasB) { sB = src[eB]; dB = dst[eB]; }

    float4 hA = *(const float4*)(g_h1s + sA * HID + j * 4);
    red_add_v4(g_agg1 + dA * HID + j * 4, hA);
    if (hasB) {
        float4 hB = *(const float4*)(g_h1s + sB * HID + j * 4);
        red_add_v4(g_agg1 + dB * HID + j * 4, hB);
    }
}

// 5) h2 = relu(dinv*agg1 + b1) @ W2; h2s = dinv*h2; agg2 = h2s (self loop)
__global__ void k_layer2(const float* __restrict__ b1,
                         const float* __restrict__ W2, int n) {
    __shared__ float sW2[HID * NCLS];
    __shared__ float sb1[HID];
    if (threadIdx.x < HID * NCLS) sW2[threadIdx.x] = W2[threadIdx.x];
    if (threadIdx.x < HID) sb1[threadIdx.x] = b1[threadIdx.x];
    __syncthreads();

    int gid = blockIdx.x * blockDim.x + threadIdx.x;
    int node = gid / NCLS;
    int c    = gid % NCLS;
    if (node >= n) return;

    float di = g_dinv[node];
    float acc = 0.0f;
    #pragma unroll
    for (int j = 0; j < HID; j++) {
        float v = fmaf(di, g_agg1[node * HID + j], sb1[j]);
        v = fmaxf(v, 0.0f);
        acc = fmaf(v, sW2[j * NCLS + c], acc);
    }
    float hs = di * acc;
    g_h2s [node * NCLS + c] = hs;
    g_agg2[node * NCLS + c] = hs;
}

// 6) layer-2 edge scatter: 2 threads/edge, 2 edges/thread, v4 RED
__global__ void k_edge2(const int* __restrict__ src,
                        const int* __restrict__ dst, int e) {
    int h = (e + 1) >> 1;
    long long gid = (long long)blockIdx.x * blockDim.x + threadIdx.x;
    int q = (int)(gid >> 1);
    int j = (int)(gid & 1);
    if (q >= h) return;
    int eA = q, eB = q + h;
    bool hasB = eB < e;

    int sA = src[eA], dA = dst[eA];
    int sB = 0, dB = 0;
    if (hasB) { sB = src[eB]; dB = dst[eB]; }

    float4 hA = *(const float4*)(g_h2s + sA * NCLS + j * 4);
    red_add_v4(g_agg2 + dA * NCLS + j * 4, hA);
    if (hasB) {
        float4 hB = *(const float4*)(g_h2s + sB * NCLS + j * 4);
        red_add_v4(g_agg2 + dB * NCLS + j * 4, hB);
    }
}

// 7) logits = dinv*agg2 + b2 -> log_softmax
__global__ void k_logsoftmax(const float* __restrict__ b2,
                             float* __restrict__ out, int n) {
    __shared__ float sb2[NCLS];
    if (threadIdx.x < NCLS) sb2[threadIdx.x] = b2[threadIdx.x];
    __syncthreads();

    int i = blockIdx.x * blockDim.x + threadIdx.x;
    if (i >= n) return;

    float di = g_dinv[i];
    float4 a = *(const float4*)(g_agg2 + i * NCLS);
    float4 b = *(const float4*)(g_agg2 + i * NCLS + 4);
    float z[NCLS] = {fmaf(di, a.x, sb2[0]), fmaf(di, a.y, sb2[1]),
                     fmaf(di, a.z, sb2[2]), fmaf(di, a.w, sb2[3]),
                     fmaf(di, b.x, sb2[4]), fmaf(di, b.y, sb2[5]),
                     fmaf(di, b.z, sb2[6]), fmaf(di, b.w, sb2[7])};
    float m = z[0];
    #pragma unroll
    for (int c = 1; c < NCLS; c++) m = fmaxf(m, z[c]);
    float sum = 0.0f;
    #pragma unroll
    for (int c = 0; c < NCLS; c++) sum += expf(z[c] - m);
    float lse = m + logf(sum);
    *(float4*)(out + i * NCLS)     = make_float4(z[0]-lse, z[1]-lse, z[2]-lse, z[3]-lse);
    *(float4*)(out + i * NCLS + 4) = make_float4(z[4]-lse, z[5]-lse, z[6]-lse, z[7]-lse);
}

// ---------------------------------------------------------------------------
extern "C" void kernel_launch(void* const* d_in, const int* in_sizes, int n_in,
                              void* d_out, int out_size) {
    const float* x  = (const float*)d_in[0];
    const int*   ei = (const int*)d_in[1];    // [2, E] int32
    const float* W1 = (const float*)d_in[2];
    const float* b1 = (const float*)d_in[3];
    const float* W2 = (const float*)d_in[4];
    const float* b2 = (const float*)d_in[5];
    float*       out = (float*)d_out;

    const int n = in_sizes[0] / F_IN;      // 100000
    const int e = in_sizes[1] / 2;         // 3200000
    const int* src = ei;
    const int* dst = ei + e;

    const int T = 256;
    int e4t = (e >> 2) + (e & 3);

    k_init_deg<<<(n + T - 1) / T, T>>>(n);                              // 0
    k_deg_scatter<<<(e4t + T - 1) / T, T>>>(dst, e);                    // 1
    k_dinv<<<(n + T - 1) / T, T>>>(n);                                  // 2
    k_xw1<<<(n + 64 * XW_ND - 1) / (64 * XW_ND), T>>>(x, W1, n);        // 3 (profiled)
    {
        long long total = (long long)((e + 1) >> 1) * 4;
        k_edge1<<<(unsigned)((total + T - 1) / T), T>>>(src, dst, e);   // 4
    }
    k_layer2<<<((long long)n * NCLS + T - 1) / T, T>>>(b1, W2, n);      // 5
    {
        long long total = (long long)((e + 1) >> 1) * 2;
        k_edge2<<<(unsigned)((total + T - 1) / T), T>>>(src, dst, e);   // 6
    }
    k_logsoftmax<<<(n + T - 1) / T, T>>>(b2, out, n);                   // 7
}